// round 16
// baseline (speedup 1.0000x reference)
#include <cuda_runtime.h>
#include <cuda_bf16.h>
#include <cuda_fp16.h>
#include <math.h>
#include <stdint.h>

// Problem constants
#define NV    50000
#define EE    800000
#define H     128
#define H2    256
#define GG    256
#define K0P   8            // A0 row width in kpairs (K=16)
#define KAU   72           // Aext row width in kpairs (K=144)

// ---------------- scratch ----------------
__device__ int   g_deg[NV];
__device__ int   g_rowptr[NV + 1];
__device__ int   g_pos[NV];
__device__ __align__(16) int2 g_edges[EE];   // {dst, eid}
__device__ int   g_tmpscan[NV];
__device__ int   g_blocksum[128];
__device__ unsigned g_gbar[6];
__device__ unsigned g_done;
__device__ __align__(16) uint32_t g_A0h[(size_t)NV * K0P];
__device__ __align__(16) uint32_t g_A0l[(size_t)NV * K0P];
__device__ __align__(16) uint32_t g_AEh[(size_t)NV * KAU];
__device__ __align__(16) uint32_t g_AEl[(size_t)NV * KAU];
__device__ __align__(16) uint32_t g_W0h[256 * K0P];     // bf16 [n][kp]
__device__ __align__(16) uint32_t g_W0l[256 * K0P];
__device__ __align__(16) uint32_t g_W1h[256 * KAU];     // bf16 [n][kp]
__device__ __align__(16) uint32_t g_W1l[256 * KAU];
__device__ __align__(16) uint32_t g_W2h[2 * 128 * 128]; // fp16 (x64 scaled) [layer][n][kp]
__device__ __align__(16) uint32_t g_W2l[2 * 128 * 128];
__device__ float g_z[(size_t)NV * H2];
__device__ float g_h[(size_t)NV * H];                   // layer-1 h (fp32)
__device__ __align__(16) uint32_t g_h16[(size_t)NV * 64]; // layer-0 h (fp16x2)
__device__ float g_stats[2 * H2];
__device__ float g_s2[GG * H];

// ---------------- helpers ----------------
__device__ __forceinline__ uint32_t smem_u32(const void* p) {
    uint32_t a;
    asm("{ .reg .u64 t; cvta.to.shared.u64 t, %1; cvt.u32.u64 %0, t; }" : "=r"(a) : "l"(p));
    return a;
}

__device__ __forceinline__ void splitpack(float x, float y, uint32_t& hi, uint32_t& lo) {
    __nv_bfloat16 hx = __float2bfloat16_rn(x);
    __nv_bfloat16 hy = __float2bfloat16_rn(y);
    __nv_bfloat16 lx = __float2bfloat16_rn(x - __bfloat162float(hx));
    __nv_bfloat16 ly = __float2bfloat16_rn(y - __bfloat162float(hy));
    hi = ((uint32_t)__bfloat16_as_ushort(hy) << 16) | __bfloat16_as_ushort(hx);
    lo = ((uint32_t)__bfloat16_as_ushort(ly) << 16) | __bfloat16_as_ushort(lx);
}

__device__ __forceinline__ void splitpack_f16(float x, float y, uint32_t& hi, uint32_t& lo) {
    __half hx = __float2half_rn(x);
    __half hy = __float2half_rn(y);
    __half lx = __float2half_rn(x - __half2float(hx));
    __half ly = __float2half_rn(y - __half2float(hy));
    hi = ((uint32_t)__half_as_ushort(hy) << 16) | __half_as_ushort(hx);
    lo = ((uint32_t)__half_as_ushort(ly) << 16) | __half_as_ushort(lx);
}

__device__ __forceinline__ uint32_t pack_f16x2(float lo, float hi) {
    uint32_t p;
    asm("cvt.rn.f16x2.f32 %0, %1, %2;" : "=r"(p) : "f"(hi), "f"(lo));
    return p;
}

__device__ __forceinline__ void mma16(float* c, const uint32_t* a, const uint32_t* b) {
    asm volatile(
        "mma.sync.aligned.m16n8k16.row.col.f32.bf16.bf16.f32 "
        "{%0,%1,%2,%3},{%4,%5,%6,%7},{%8,%9},{%0,%1,%2,%3};"
        : "+f"(c[0]), "+f"(c[1]), "+f"(c[2]), "+f"(c[3])
        : "r"(a[0]), "r"(a[1]), "r"(a[2]), "r"(a[3]), "r"(b[0]), "r"(b[1]));
}

__device__ __forceinline__ void mma16f(float* c, const uint32_t* a, const uint32_t* b) {
    asm volatile(
        "mma.sync.aligned.m16n8k16.row.col.f32.f16.f16.f32 "
        "{%0,%1,%2,%3},{%4,%5,%6,%7},{%8,%9},{%0,%1,%2,%3};"
        : "+f"(c[0]), "+f"(c[1]), "+f"(c[2]), "+f"(c[3])
        : "r"(a[0]), "r"(a[1]), "r"(a[2]), "r"(a[3]), "r"(b[0]), "r"(b[1]));
}

__device__ __forceinline__ void ldsm4(uint32_t& r0, uint32_t& r1, uint32_t& r2, uint32_t& r3,
                                      uint32_t addr) {
    asm volatile("ldmatrix.sync.aligned.m8n8.x4.shared.b16 {%0,%1,%2,%3}, [%4];"
                 : "=r"(r0), "=r"(r1), "=r"(r2), "=r"(r3) : "r"(addr));
}

__device__ __forceinline__ void cp16p(uint32_t dst, const void* src, int sz) {
    asm volatile("cp.async.cg.shared.global [%0], [%1], 16, %2;"
                 :: "r"(dst), "l"(src), "r"(sz) : "memory");
}
#define CP_COMMIT() asm volatile("cp.async.commit_group;" ::: "memory")
#define CP_WAIT0()  asm volatile("cp.async.wait_group 0;" ::: "memory")

// ---------------- fused persistent CSR + node-feature kernel ----------------
// grid = ceil(n/512) (= 98 <= #SMs, co-resident), blockDim = 512.
// Phases: zero-deg | count | block scan | offsets+rowptr | fill | node gather,
// separated by replay-safe software grid barriers.
#define GBAR(K) do {                                                        \
    __threadfence();                                                        \
    __syncthreads();                                                        \
    if (tid == 0) {                                                         \
        atomicAdd(&g_gbar[(K)], 1u);                                        \
        while (atomicAdd(&g_gbar[(K)], 0u) < (unsigned)nblocks) { }         \
        if (blockIdx.x == 0 && (K) >= 2) atomicExch(&g_gbar[(K) - 1], 0u);  \
    }                                                                       \
    __syncthreads();                                                        \
} while (0)

__global__ void __launch_bounds__(512, 1)
k_graph(const int* __restrict__ src, const int* __restrict__ dst,
        const int* __restrict__ x_ids, const float* __restrict__ attr,
        int n, int ec, int nblocks) {
    __shared__ int s[512];
    __shared__ int sh[128], orig[128];
    int tid = threadIdx.x;
    int gt = blockIdx.x * 512 + tid;
    int nthreads = nblocks * 512;

    // Phase A: zero degrees
    if (gt < n) g_deg[gt] = 0;
    GBAR(1);

    // Phase B: count
    for (int e = gt; e < ec; e += nthreads) atomicAdd(&g_deg[src[e]], 1);
    GBAR(2);

    // Phase C: per-block inclusive scan (512-wide)
    s[tid] = (gt < n) ? g_deg[gt] : 0;
    __syncthreads();
#pragma unroll
    for (int off = 1; off < 512; off <<= 1) {
        int t = 0;
        if (tid >= off) t = s[tid - off];
        __syncthreads();
        s[tid] += t;
        __syncthreads();
    }
    if (gt < n) g_tmpscan[gt] = s[tid];
    if (tid == 511) g_blocksum[blockIdx.x] = s[511];
    GBAR(3);

    // Phase D: cross-block offsets -> rowptr/pos
    if (tid < 128) {
        int v = (tid < nblocks) ? g_blocksum[tid] : 0;
        sh[tid] = v;
        orig[tid] = v;
    }
    __syncthreads();
#pragma unroll
    for (int off = 1; off < 128; off <<= 1) {
        int x = 0;
        if (tid < 128 && tid >= off) x = sh[tid - off];
        __syncthreads();
        if (tid < 128) sh[tid] += x;
        __syncthreads();
    }
    if (gt < n) {
        int r = g_tmpscan[gt] - g_deg[gt] + (sh[blockIdx.x] - orig[blockIdx.x]);
        g_rowptr[gt] = r;
        g_pos[gt] = r;
    }
    if (blockIdx.x == 0 && tid == 0) g_rowptr[n] = sh[127];
    GBAR(4);

    // Phase E: fill edge list
    for (int e = gt; e < ec; e += nthreads) {
        int idx = atomicAdd(&g_pos[src[e]], 1);
        g_edges[idx] = make_int2(dst[e], e);
    }
    GBAR(5);

    // Phase F: per-node gather (8-lane groups, grid-stride, uniform trip count)
    {
        int ngroups = nthreads >> 3;
        int g0 = gt >> 3;
        int sl = tid & 7;
        int maxiter = (n + ngroups - 1) / ngroups;
        for (int it = 0; it < maxiter; it++) {
            int gid = g0 + it * ngroups;
            bool act = gid < n;
            int e0 = 0, e1 = 0;
            if (act) {
                e0 = __ldcg(&g_rowptr[gid]);
                e1 = __ldcg(&g_rowptr[gid + 1]);
            }
            float a[9];
#pragma unroll
            for (int j = 0; j < 9; j++) a[j] = 0.f;
            int bc = 0;
            for (int e = e0 + sl; e < e1; e += 8) {
                int2 ce = __ldcg(&g_edges[e]);
                bc += x_ids[ce.x];
                const float* ap = attr + (size_t)ce.y * 9;
#pragma unroll
                for (int j = 0; j < 9; j++) a[j] += ap[j];
            }
#pragma unroll
            for (int o = 4; o > 0; o >>= 1) {
#pragma unroll
                for (int j = 0; j < 9; j++) a[j] += __shfl_xor_sync(0xffffffff, a[j], o);
                bc += __shfl_xor_sync(0xffffffff, bc, o);
            }
            if (act) {
                a[7] += 1.0f;                                   // self-loop one-hot
                float dp1 = (float)(e1 - e0 + 1);
                float bfull = (float)(bc + x_ids[gid]);
                float t[16];
#pragma unroll
                for (int j = 0; j < 9; j++) t[j] = a[j];
                t[9] = dp1; t[10] = 1.f;
                t[11] = 0.f; t[12] = 0.f; t[13] = 0.f; t[14] = 0.f; t[15] = 0.f;
                float a0v[16];
                a0v[0] = dp1 - bfull;
                a0v[1] = bfull;
#pragma unroll
                for (int j = 0; j < 9; j++) a0v[2 + j] = a[j];
                a0v[11] = dp1; a0v[12] = 1.f;
                a0v[13] = 0.f; a0v[14] = 0.f; a0v[15] = 0.f;
                uint32_t h, l;
                splitpack(t[2 * sl], t[2 * sl + 1], h, l);
                g_AEh[(size_t)gid * KAU + 64 + sl] = h;
                g_AEl[(size_t)gid * KAU + 64 + sl] = l;
                splitpack(a0v[2 * sl], a0v[2 * sl + 1], h, l);
                g_A0h[(size_t)gid * K0P + sl] = h;
                g_A0l[(size_t)gid * K0P + sl] = l;
            }
        }
    }

    // Exit protocol: last block to finish resets the final barrier counter.
    __syncthreads();
    if (tid == 0) {
        unsigned d = atomicAdd(&g_done, 1u);
        if (d == (unsigned)nblocks - 1u) {
            atomicExch(&g_gbar[5], 0u);
            atomicExch(&g_done, 0u);
        }
    }
}

// ---------------- fused init: stats-zero + weight preps ----------------
__device__ __forceinline__ float w0row(int row, int col,
                                       const float* node_emb, const float* enc_w,
                                       const float* enc_b, const float* w1,
                                       const float* b1) {
    float val = 0.f;
    if (row < 2) {
        for (int k = 0; k < H; k++) val += node_emb[row * H + k] * w1[k * H2 + col];
    } else if (row < 11) {
        int j = row - 2;
        for (int k = 0; k < H; k++) val += enc_w[j * H + k] * w1[(H + k) * H2 + col];
    } else if (row == 11) {
        for (int k = 0; k < H; k++) val += enc_b[k] * w1[(H + k) * H2 + col];
    } else if (row == 12) {
        val = b1[col];
    }
    return val;
}
__device__ __forceinline__ float w1row(int row, int col,
                                       const float* enc_w, const float* enc_b,
                                       const float* w1, const float* b1) {
    const float* w1L = w1 + H2 * H2;
    float val = 0.f;
    if (row < 128) {
        val = w1L[row * H2 + col];
    } else if (row < 137) {
        int j = row - 128;
        for (int k = 0; k < H; k++) val += enc_w[9 * H + j * H + k] * w1L[(H + k) * H2 + col];
    } else if (row == 137) {
        for (int k = 0; k < H; k++) val += enc_b[H + k] * w1L[(H + k) * H2 + col];
    } else if (row == 138) {
        val = b1[H2 + col];
    }
    return val;
}

#define NBZ 2
__global__ void k_init(const float* __restrict__ node_emb, const float* __restrict__ enc_w,
                       const float* __restrict__ enc_b, const float* __restrict__ w1,
                       const float* __restrict__ b1, const float* __restrict__ w2) {
    int b = blockIdx.x, tid = threadIdx.x;
    if (b < NBZ) {
        int i = b * 256 + tid;
        if (i < 2 * H2) g_stats[i] = 0.f;
        return;
    }
    if (b < NBZ + 8) {               // W0 (bf16 split)
        int item = (b - NBZ) * 256 + tid;
        int nn = item >> 3, kp = item & 7;
        float v0 = w0row(2 * kp, nn, node_emb, enc_w, enc_b, w1, b1);
        float v1 = w0row(2 * kp + 1, nn, node_emb, enc_w, enc_b, w1, b1);
        uint32_t h, l;
        splitpack(v0, v1, h, l);
        g_W0h[nn * K0P + kp] = h;
        g_W0l[nn * K0P + kp] = l;
        return;
    }
    if (b < NBZ + 8 + 72) {          // W1 (bf16 split)
        int item = (b - NBZ - 8) * 256 + tid;
        int nn = item / KAU, kp = item - nn * KAU;
        float v0 = w1row(2 * kp, nn, enc_w, enc_b, w1, b1);
        float v1 = w1row(2 * kp + 1, nn, enc_w, enc_b, w1, b1);
        uint32_t h, l;
        splitpack(v0, v1, h, l);
        g_W1h[nn * KAU + kp] = h;
        g_W1l[nn * KAU + kp] = l;
        return;
    }
    {                                // W2 (fp16 split, x64 scale)
        int item = (b - NBZ - 80) * 256 + tid;
        if (item >= 2 * 128 * 128) return;
        int layer = item >> 14;
        int r = item & 16383;
        int nn = r >> 7, kp = r & 127;
        const float* w = w2 + (size_t)layer * H2 * H;
        float v0 = w[(2 * kp) * H + nn] * 64.f;
        float v1 = w[(2 * kp + 1) * H + nn] * 64.f;
        uint32_t h, l;
        splitpack_f16(v0, v1, h, l);
        g_W2h[item] = h;
        g_W2l[item] = l;
    }
}

// ---------------- z-GEMM: compensated bf16 3-pass, pre-split A/B, KPT=8 ----------------
__global__ void __launch_bounds__(256, 2)
zgemm(const uint32_t* __restrict__ Ah, const uint32_t* __restrict__ Al, int ldau,
      const uint32_t* __restrict__ Bh, const uint32_t* __restrict__ Bl, int ldku,
      float* __restrict__ C, int M, int K) {
    constexpr int KPT = 8;
    constexpr int S = KPT + 4;
    constexpr int ABUF = 128 * S * 4;
    constexpr int ASEC = 2 * ABUF;
    extern __shared__ __align__(16) char dsm[];
    uint32_t* aHp = (uint32_t*)dsm;
    uint32_t* bHp = (uint32_t*)(dsm + 2 * ASEC);
    uint32_t* bLp = (uint32_t*)(dsm + 3 * ASEC);

    int tid = threadIdx.x, wid = tid >> 5, lane = tid & 31;
    int qid = lane >> 2, rid = lane & 3;
    int warp_m = wid & 1, warp_n = wid >> 1;
    int m0 = blockIdx.x * 128, n0 = blockIdx.y * 128;

    float acc[4][4][4];
#pragma unroll
    for (int i = 0; i < 4; i++)
#pragma unroll
        for (int j = 0; j < 4; j++)
#pragma unroll
            for (int q = 0; q < 4; q++) acc[i][j][q] = 0.f;

    int row = tid >> 1;
    int half = tid & 1;
    int kp0 = half * 4;
    int gm = m0 + row;
    bool amv = gm < M;
    int gmc = amv ? gm : (M - 1);
    int azA = amv ? 16 : 0;
    uint32_t sA = smem_u32(aHp) + (uint32_t)(row * S + kp0) * 4;
    uint32_t sB = smem_u32(bHp) + (uint32_t)(row * S + kp0) * 4;
    const uint32_t* gBh = Bh + (size_t)(n0 + row) * ldku + kp0;
    const uint32_t* gBl = Bl + (size_t)(n0 + row) * ldku + kp0;
    const uint32_t* gAh = Ah + (size_t)gmc * ldau + kp0;
    const uint32_t* gAl = Al + (size_t)gmc * ldau + kp0;

    int nsteps = K / 16;

    cp16p(sA, gAh, azA);
    cp16p(sA + ASEC, gAl, azA);
    cp16p(sB, gBh, 16);
    cp16p(sB + ASEC, gBl, 16);
    CP_COMMIT();

    int bo = 0;
    for (int s = 0; s < nsteps; s++) {
        CP_WAIT0();
        __syncthreads();
        if (s + 1 < nsteps) {
            int nb = bo ^ ABUF;
            int ko = (s + 1) * KPT;
            cp16p(sA + nb, gAh + ko, azA);
            cp16p(sA + nb + ASEC, gAl + ko, azA);
            cp16p(sB + nb, gBh + ko, 16);
            cp16p(sB + nb + ASEC, gBl + ko, 16);
            CP_COMMIT();
        }
        uint32_t sa_h = smem_u32(aHp) + bo +
            (uint32_t)(((warp_m * 64 + (lane & 15)) * S + ((lane & 16) ? 4 : 0)) * 4);
        const uint32_t* bh_base = bHp + (bo >> 2);
        const uint32_t* bl_base = bLp + (bo >> 2);
        uint32_t bfh[4][2], bfl[4][2];
#pragma unroll
        for (int nt = 0; nt < 4; nt++) {
            int nb = warp_n * 32 + nt * 8 + qid;
            bfh[nt][0] = bh_base[nb * S + rid];
            bfh[nt][1] = bh_base[nb * S + rid + 4];
            bfl[nt][0] = bl_base[nb * S + rid];
            bfl[nt][1] = bl_base[nb * S + rid + 4];
        }
#pragma unroll
        for (int mt = 0; mt < 4; mt++) {
            uint32_t ah[4], al[4];
            uint32_t ad = sa_h + mt * (16 * S * 4);
            ldsm4(ah[0], ah[1], ah[2], ah[3], ad);
            ldsm4(al[0], al[1], al[2], al[3], ad + ASEC);
#pragma unroll
            for (int nt = 0; nt < 4; nt++) {
                mma16(acc[mt][nt], ah, bfh[nt]);
                mma16(acc[mt][nt], ah, bfl[nt]);
                mma16(acc[mt][nt], al, bfh[nt]);
            }
        }
        __syncthreads();
        bo ^= ABUF;
    }

    int m_base = m0 + warp_m * 64;
    int n_base = n0 + warp_n * 32;

#pragma unroll
    for (int mt = 0; mt < 4; mt++) {
        int r0g = m_base + mt * 16 + qid;
        int r1g = r0g + 8;
#pragma unroll
        for (int nt = 0; nt < 4; nt++) {
            int cg = n_base + nt * 8 + rid * 2;
            if (r0g < M) *(float2*)(C + (size_t)r0g * H2 + cg)
                = make_float2(acc[mt][nt][0], acc[mt][nt][1]);
            if (r1g < M) *(float2*)(C + (size_t)r1g * H2 + cg)
                = make_float2(acc[mt][nt][2], acc[mt][nt][3]);
        }
    }

#pragma unroll
    for (int nt = 0; nt < 4; nt++) {
        float s0 = 0.f, q0 = 0.f, s1 = 0.f, q1 = 0.f;
#pragma unroll
        for (int mt = 0; mt < 4; mt++) {
            int r0g = m_base + mt * 16 + qid;
            const float* c = acc[mt][nt];
            if (r0g < M)     { s0 += c[0]; q0 += c[0] * c[0]; s1 += c[1]; q1 += c[1] * c[1]; }
            if (r0g + 8 < M) { s0 += c[2]; q0 += c[2] * c[2]; s1 += c[3]; q1 += c[3] * c[3]; }
        }
#pragma unroll
        for (int o = 4; o < 32; o <<= 1) {
            s0 += __shfl_xor_sync(0xffffffff, s0, o);
            q0 += __shfl_xor_sync(0xffffffff, q0, o);
            s1 += __shfl_xor_sync(0xffffffff, s1, o);
            q1 += __shfl_xor_sync(0xffffffff, q1, o);
        }
        if (lane < 4) {
            int cg = n_base + nt * 8 + lane * 2;
            atomicAdd(&g_stats[cg], s0);
            atomicAdd(&g_stats[H2 + cg], q0);
            atomicAdd(&g_stats[cg + 1], s1);
            atomicAdd(&g_stats[H2 + cg + 1], q1);
        }
    }
}

// ---------------- h-GEMM: fp16 2-pass (A single fp16, W2 split fp16 x64) ----------------
#define HS   20
#define HABUF (128 * HS * 4)
template <bool STOREH16>
__global__ void __launch_bounds__(256, 2)
hgemm(const float* __restrict__ Af,
      const uint32_t* __restrict__ Bh, const uint32_t* __restrict__ Bl,
      float* __restrict__ C, uint32_t* __restrict__ C16, int M,
      const float* __restrict__ bias, int do_relu,
      const float* __restrict__ bng, const float* __restrict__ bnb) {
    extern __shared__ __align__(16) char dsm[];
    uint32_t* aP  = (uint32_t*)dsm;
    uint32_t* bHp = (uint32_t*)(dsm + 2 * HABUF);
    uint32_t* bLp = (uint32_t*)(dsm + 4 * HABUF);
    __shared__ float s_sc[H2], s_sh[H2];

    int tid = threadIdx.x, wid = tid >> 5, lane = tid & 31;
    int qid = lane >> 2, rid = lane & 3;
    int warp_m = wid & 1, warp_n = wid >> 1;
    int m0 = blockIdx.x * 128;

    {
        float inv = 1.f / (float)M;
        float mu = g_stats[tid] * inv;
        float var = g_stats[H2 + tid] * inv - mu * mu;
        float rs = rsqrtf(var + 1e-5f);
        float sc = bng[tid] * rs;
        s_sc[tid] = sc;
        s_sh[tid] = bnb[tid] - mu * sc;
    }

    float acc[4][4][4];
#pragma unroll
    for (int i = 0; i < 4; i++)
#pragma unroll
        for (int j = 0; j < 4; j++)
#pragma unroll
            for (int q = 0; q < 4; q++) acc[i][j][q] = 0.f;

    int row = tid >> 1;
    int half = tid & 1;
    int gm = m0 + row;
    bool amv = gm < M;
    int gmc = amv ? gm : (M - 1);
    uint32_t sB = smem_u32(bHp) + (uint32_t)(row * HS + half * 8) * 4;
    const uint32_t* gBh = Bh + (size_t)row * 128 + half * 8;
    const uint32_t* gBl = Bl + (size_t)row * 128 + half * 8;
    const float* gAf = Af + (size_t)gmc * H2 + half * 16;

    const float4 z4f = make_float4(0.f, 0.f, 0.f, 0.f);
    float4 pz[4];

#pragma unroll
    for (int i = 0; i < 4; i++) pz[i] = *(const float4*)(gAf + i * 4);
#pragma unroll
    for (int i = 0; i < 2; i++) {
        cp16p(sB + i * 16, gBh + i * 4, 16);
        cp16p(sB + 2 * HABUF + i * 16, gBl + i * 4, 16);
    }
    CP_COMMIT();
    __syncthreads();

    int bo = 0;
    for (int s = 0; s < 8; s++) {
        CP_WAIT0();
        {
            int gkb = s * 32 + half * 16;
            uint32_t* dA = aP + (bo >> 2) + row * HS + half * 8;
#pragma unroll
            for (int i = 0; i < 4; i++) {
                float4 v = pz[i];
                int gk = gkb + i * 4;
                v.x = fmaxf(fmaf(v.x, s_sc[gk + 0], s_sh[gk + 0]), 0.f);
                v.y = fmaxf(fmaf(v.y, s_sc[gk + 1], s_sh[gk + 1]), 0.f);
                v.z = fmaxf(fmaf(v.z, s_sc[gk + 2], s_sh[gk + 2]), 0.f);
                v.w = fmaxf(fmaf(v.w, s_sc[gk + 3], s_sh[gk + 3]), 0.f);
                if (!amv) { v.x = v.y = v.z = v.w = 0.f; }
                dA[i * 2]     = pack_f16x2(v.x, v.y);
                dA[i * 2 + 1] = pack_f16x2(v.z, v.w);
            }
        }
        __syncthreads();
        if (s + 1 < 8) {
            int nb = bo ^ HABUF;
            int ko = (s + 1) * 16;
#pragma unroll
            for (int i = 0; i < 2; i++) {
                cp16p(sB + nb + i * 16, gBh + ko + i * 4, 16);
                cp16p(sB + nb + 2 * HABUF + i * 16, gBl + ko + i * 4, 16);
            }
            CP_COMMIT();
            const float* zp = gAf + (size_t)(s + 1) * 32;
#pragma unroll
            for (int i = 0; i < 4; i++)
                pz[i] = amv ? *(const float4*)(zp + i * 4) : z4f;
        }

        uint32_t sa = smem_u32(aP) + bo +
            (uint32_t)(((warp_m * 64 + (lane & 15)) * HS + ((lane & 16) ? 4 : 0)) * 4);
        const uint32_t* bh_base = bHp + (bo >> 2);
        const uint32_t* bl_base = bLp + (bo >> 2);
#pragma unroll
        for (int sub = 0; sub < 2; sub++) {
            uint32_t bfh[4][2], bfl[4][2];
#pragma unroll
            for (int nt = 0; nt < 4; nt++) {
                int nb = warp_n * 32 + nt * 8 + qid;
                bfh[nt][0] = bh_base[nb * HS + sub * 8 + rid];
                bfh[nt][1] = bh_base[nb * HS + sub * 8 + rid + 4];
                bfl[nt][0] = bl_base[nb * HS + sub * 8 + rid];
                bfl[nt][1] = bl_base[nb * HS + sub * 8 + rid + 4];
            }
#pragma unroll
            for (int mt = 0; mt < 4; mt++) {
                uint32_t ah[4];
                ldsm4(ah[0], ah[1], ah[2], ah[3], sa + sub * 32 + mt * (16 * HS * 4));
#pragma unroll
                for (int nt = 0; nt < 4; nt++) {
                    mma16f(acc[mt][nt], ah, bfh[nt]);
                    mma16f(acc[mt][nt], ah, bfl[nt]);
                }
            }
        }
        __syncthreads();
        bo ^= HABUF;
    }

    int m_base = m0 + warp_m * 64;
    int n_base = warp_n * 32;
    const float inv64 = 0.015625f;

#pragma unroll
    for (int mt = 0; mt < 4; mt++) {
        int r0g = m_base + mt * 16 + qid;
        int r1g = r0g + 8;
#pragma unroll
        for (int nt = 0; nt < 4; nt++) {
            int cg = n_base + nt * 8 + rid * 2;
            float b0v = bias[cg], b1v = bias[cg + 1];
            float v0 = fmaf(acc[mt][nt][0], inv64, b0v);
            float v1 = fmaf(acc[mt][nt][1], inv64, b1v);
            float v2 = fmaf(acc[mt][nt][2], inv64, b0v);
            float v3 = fmaf(acc[mt][nt][3], inv64, b1v);
            if (do_relu) {
                v0 = fmaxf(v0, 0.f); v1 = fmaxf(v1, 0.f);
                v2 = fmaxf(v2, 0.f); v3 = fmaxf(v3, 0.f);
            }
            if (STOREH16) {
                if (r0g < M) C16[(size_t)r0g * 64 + (cg >> 1)] = pack_f16x2(v0, v1);
                if (r1g < M) C16[(size_t)r1g * 64 + (cg >> 1)] = pack_f16x2(v2, v3);
            } else {
                if (r0g < M) *(float2*)(C + (size_t)r0g * H + cg) = make_float2(v0, v1);
                if (r1g < M) *(float2*)(C + (size_t)r1g * H + cg) = make_float2(v2, v3);
            }
        }
    }
}

// ---------------- SpMM: fp16 gather of h0; write bf16-split agg; re-zero stats ----------------
__global__ void k_spmm(int n) {
    int t0 = blockIdx.x * blockDim.x + threadIdx.x;
    if (t0 < 2 * H2) g_stats[t0] = 0.f;
    int wid = t0 >> 5;
    int lane = threadIdx.x & 31;
    if (wid >= n) return;
    const uint2* h2 = (const uint2*)g_h16;
    uint2 sv = h2[(size_t)wid * 32 + lane];
    float2 f0 = __half22float2(*(__half2*)&sv.x);
    float2 f1 = __half22float2(*(__half2*)&sv.y);
    float4 acc = make_float4(f0.x, f0.y, f1.x, f1.y);
    int e0 = g_rowptr[wid], e1 = g_rowptr[wid + 1];
    for (int e = e0; e < e1; e++) {
        int c = g_edges[e].x;
        uint2 hv = h2[(size_t)c * 32 + lane];
        float2 a0 = __half22float2(*(__half2*)&hv.x);
        float2 a1 = __half22float2(*(__half2*)&hv.y);
        acc.x += a0.x; acc.y += a0.y; acc.z += a1.x; acc.w += a1.y;
    }
    uint32_t h0, l0, h1, l1;
    splitpack(acc.x, acc.y, h0, l0);
    splitpack(acc.z, acc.w, h1, l1);
    size_t base = (size_t)wid * KAU + 2 * lane;
    *(uint2*)&g_AEh[base] = make_uint2(h0, h1);
    *(uint2*)&g_AEl[base] = make_uint2(l0, l1);
}

// ---------------- fused head ----------------
__global__ void k_head(const int* __restrict__ batch, const float* __restrict__ disc_w, int n) {
    __shared__ float srow[H];
    int g = blockIdx.x;
    int c = threadIdx.x;
    int lo = 0, hi = n;
    while (lo < hi) { int m = (lo + hi) >> 1; if (batch[m] < g) lo = m + 1; else hi = m; }
    int lo2 = lo, hi2 = n;
    while (lo2 < hi2) { int m = (lo2 + hi2) >> 1; if (batch[m] < g + 1) lo2 = m + 1; else hi2 = m; }
    float s = 0.f;
    for (int r = lo; r < lo2; r++) s += g_h[(size_t)r * H + c];
    float cnt = fmaxf((float)(lo2 - lo), 1.f);
    float sm = 1.f / (1.f + expf(-s / cnt));
    srow[c] = sm;
    __syncthreads();
    float acc = 0.f;
    for (int k = 0; k < H; k++) acc = fmaf(srow[k], disc_w[k * H + c], acc);
    g_s2[g * H + c] = acc;
}

// 8-lane groups: 4 nodes per warp
__global__ void k_out(const int* __restrict__ batch, float* __restrict__ out, int n) {
    int gid = (blockIdx.x * blockDim.x + threadIdx.x) >> 3;
    int sl = threadIdx.x & 7;
    if (gid >= n) return;
    int g = batch[gid];
    int g2 = (g + 1) & (GG - 1);
    const float4* h4 = (const float4*)g_h;
    const float4* s4 = (const float4*)g_s2;
    float p = 0.f, q = 0.f;
#pragma unroll
    for (int i = 0; i < 4; i++) {
        float4 hv = h4[(size_t)gid * 32 + sl * 4 + i];
        float4 av = s4[(size_t)g * 32 + sl * 4 + i];
        float4 bv = s4[(size_t)g2 * 32 + sl * 4 + i];
        p += hv.x * av.x + hv.y * av.y + hv.z * av.z + hv.w * av.w;
        q += hv.x * bv.x + hv.y * bv.y + hv.z * bv.z + hv.w * bv.w;
    }
#pragma unroll
    for (int off = 4; off > 0; off >>= 1) {
        p += __shfl_xor_sync(0xffffffff, p, off);
        q += __shfl_xor_sync(0xffffffff, q, off);
    }
    if (sl == 0) { out[gid] = p; out[n + gid] = q; }
}

// ---------------- host ----------------
extern "C" void kernel_launch(void* const* d_in, const int* in_sizes, int n_in,
                              void* d_out, int out_size) {
    const int*   x_ids     = (const int*)d_in[0];
    const int*   ei        = (const int*)d_in[1];
    const int*   batch     = (const int*)d_in[2];
    const float* edge_attr = (const float*)d_in[3];
    const float* node_emb  = (const float*)d_in[4];
    const float* enc_w     = (const float*)d_in[5];
    const float* enc_b     = (const float*)d_in[6];
    const float* w1        = (const float*)d_in[7];
    const float* b1        = (const float*)d_in[8];
    const float* bn_g      = (const float*)d_in[9];
    const float* bn_b      = (const float*)d_in[10];
    const float* w2        = (const float*)d_in[11];
    const float* b2        = (const float*)d_in[12];
    const float* disc_w    = (const float*)d_in[13];
    float* out = (float*)d_out;

    int n  = in_sizes[0];
    int ec = in_sizes[1] / 2;
    const int* src = ei;
    const int* dst = ei + ec;

    const int SMZ = 4 * 2 * 128 * 12 * 4;   // 49152
    const int SMH = 6 * HABUF;              // 61440
    cudaFuncSetAttribute(zgemm, cudaFuncAttributeMaxDynamicSharedMemorySize, SMZ);
    cudaFuncSetAttribute(hgemm<true>, cudaFuncAttributeMaxDynamicSharedMemorySize, SMH);
    cudaFuncSetAttribute(hgemm<false>, cudaFuncAttributeMaxDynamicSharedMemorySize, SMH);

    float *p_z, *p_h;
    uint32_t *p_A0h, *p_A0l, *p_AEh, *p_AEl;
    uint32_t *p_W0h, *p_W0l, *p_W1h, *p_W1l, *p_W2h, *p_W2l, *p_h16;
    cudaGetSymbolAddress((void**)&p_z,   g_z);
    cudaGetSymbolAddress((void**)&p_h,   g_h);
    cudaGetSymbolAddress((void**)&p_h16, g_h16);
    cudaGetSymbolAddress((void**)&p_A0h, g_A0h);
    cudaGetSymbolAddress((void**)&p_A0l, g_A0l);
    cudaGetSymbolAddress((void**)&p_AEh, g_AEh);
    cudaGetSymbolAddress((void**)&p_AEl, g_AEl);
    cudaGetSymbolAddress((void**)&p_W0h, g_W0h);
    cudaGetSymbolAddress((void**)&p_W0l, g_W0l);
    cudaGetSymbolAddress((void**)&p_W1h, g_W1h);
    cudaGetSymbolAddress((void**)&p_W1l, g_W1l);
    cudaGetSymbolAddress((void**)&p_W2h, g_W2h);
    cudaGetSymbolAddress((void**)&p_W2l, g_W2l);

    int mb     = (n + 127) / 128;
    int warpsB = (n * 32 + 255) / 256;
    int nodeB  = (n * 8 + 255) / 256;
    int gb     = (n + 511) / 512;            // 98 blocks, co-resident on 148+ SMs
    int initB  = NBZ + 8 + 72 + 128;

    // --- init (weights/stats) + fused persistent CSR/node kernel ---
    k_init<<<initB, 256>>>(node_emb, enc_w, enc_b, w1, b1, w2);
    k_graph<<<gb, 512>>>(src, dst, x_ids, edge_attr, n, ec, gb);

    // --- layer 0 ---
    zgemm<<<dim3(mb, 2), 256, SMZ>>>(p_A0h, p_A0l, K0P, p_W0h, p_W0l, K0P, p_z, n, 16);
    hgemm<true><<<dim3(mb, 1), 256, SMH>>>(p_z, p_W2h, p_W2l, nullptr, p_h16, n,
                                           b2, 1, bn_g, bn_b);

    // --- layer 1 ---
    k_spmm<<<warpsB, 256>>>(n);
    zgemm<<<dim3(mb, 2), 256, SMZ>>>(p_AEh, p_AEl, KAU, p_W1h, p_W1l, KAU, p_z, n, 144);
    hgemm<false><<<dim3(mb, 1), 256, SMH>>>(p_z, p_W2h + 128 * 128, p_W2l + 128 * 128,
                                            p_h, nullptr, n, b2 + H, 0,
                                            bn_g + H2, bn_b + H2);

    // --- head ---
    k_head<<<GG, H>>>(batch, disc_w, n);
    k_out<<<nodeB, 256>>>(batch, out, n);
}

// round 17
// speedup vs baseline: 1.0561x; 1.0561x over previous
#include <cuda_runtime.h>
#include <cuda_bf16.h>
#include <cuda_fp16.h>
#include <math.h>
#include <stdint.h>

// Problem constants
#define NV    50000
#define EE    800000
#define H     128
#define H2    256
#define GG    256
#define K0P   8            // A0 row width in kpairs (K=16)
#define KAU   72           // Aext row width in kpairs (K=144)

// ---------------- scratch ----------------
__device__ int   g_deg[NV];
__device__ int   g_rowptr[NV + 1];
__device__ int   g_pos[NV];
__device__ __align__(16) int2 g_edges[EE];   // {dst, eid}
__device__ int   g_tmpscan[NV];
__device__ int   g_blocksum[128];
__device__ __align__(16) uint32_t g_A0h[(size_t)NV * K0P];
__device__ __align__(16) uint32_t g_A0l[(size_t)NV * K0P];
__device__ __align__(16) uint32_t g_AEh[(size_t)NV * KAU];
__device__ __align__(16) uint32_t g_AEl[(size_t)NV * KAU];
__device__ __align__(16) uint32_t g_W0h[256 * K0P];     // bf16 [n][kp]
__device__ __align__(16) uint32_t g_W0l[256 * K0P];
__device__ __align__(16) uint32_t g_W1h[256 * KAU];     // bf16 [n][kp]
__device__ __align__(16) uint32_t g_W1l[256 * KAU];
__device__ __align__(16) uint32_t g_W2h[2 * 128 * 128]; // fp16 (x64 scaled) [layer][n][kp]
__device__ __align__(16) uint32_t g_W2l[2 * 128 * 128];
__device__ float g_z[(size_t)NV * H2];
__device__ float g_h[(size_t)NV * H];                   // layer-1 h (fp32)
__device__ __align__(16) uint32_t g_h16[(size_t)NV * 64]; // layer-0 h (fp16x2)
__device__ float g_stats[2 * H2];
__device__ float g_s2[GG * H];

// ---------------- helpers ----------------
__device__ __forceinline__ uint32_t smem_u32(const void* p) {
    uint32_t a;
    asm("{ .reg .u64 t; cvta.to.shared.u64 t, %1; cvt.u32.u64 %0, t; }" : "=r"(a) : "l"(p));
    return a;
}

__device__ __forceinline__ void splitpack(float x, float y, uint32_t& hi, uint32_t& lo) {
    __nv_bfloat16 hx = __float2bfloat16_rn(x);
    __nv_bfloat16 hy = __float2bfloat16_rn(y);
    __nv_bfloat16 lx = __float2bfloat16_rn(x - __bfloat162float(hx));
    __nv_bfloat16 ly = __float2bfloat16_rn(y - __bfloat162float(hy));
    hi = ((uint32_t)__bfloat16_as_ushort(hy) << 16) | __bfloat16_as_ushort(hx);
    lo = ((uint32_t)__bfloat16_as_ushort(ly) << 16) | __bfloat16_as_ushort(lx);
}

__device__ __forceinline__ void splitpack_f16(float x, float y, uint32_t& hi, uint32_t& lo) {
    __half hx = __float2half_rn(x);
    __half hy = __float2half_rn(y);
    __half lx = __float2half_rn(x - __half2float(hx));
    __half ly = __float2half_rn(y - __half2float(hy));
    hi = ((uint32_t)__half_as_ushort(hy) << 16) | __half_as_ushort(hx);
    lo = ((uint32_t)__half_as_ushort(ly) << 16) | __half_as_ushort(lx);
}

__device__ __forceinline__ uint32_t pack_f16x2(float lo, float hi) {
    uint32_t p;
    asm("cvt.rn.f16x2.f32 %0, %1, %2;" : "=r"(p) : "f"(hi), "f"(lo));
    return p;
}

__device__ __forceinline__ void mma16(float* c, const uint32_t* a, const uint32_t* b) {
    asm volatile(
        "mma.sync.aligned.m16n8k16.row.col.f32.bf16.bf16.f32 "
        "{%0,%1,%2,%3},{%4,%5,%6,%7},{%8,%9},{%0,%1,%2,%3};"
        : "+f"(c[0]), "+f"(c[1]), "+f"(c[2]), "+f"(c[3])
        : "r"(a[0]), "r"(a[1]), "r"(a[2]), "r"(a[3]), "r"(b[0]), "r"(b[1]));
}

__device__ __forceinline__ void mma16f(float* c, const uint32_t* a, const uint32_t* b) {
    asm volatile(
        "mma.sync.aligned.m16n8k16.row.col.f32.f16.f16.f32 "
        "{%0,%1,%2,%3},{%4,%5,%6,%7},{%8,%9},{%0,%1,%2,%3};"
        : "+f"(c[0]), "+f"(c[1]), "+f"(c[2]), "+f"(c[3])
        : "r"(a[0]), "r"(a[1]), "r"(a[2]), "r"(a[3]), "r"(b[0]), "r"(b[1]));
}

__device__ __forceinline__ void ldsm4(uint32_t& r0, uint32_t& r1, uint32_t& r2, uint32_t& r3,
                                      uint32_t addr) {
    asm volatile("ldmatrix.sync.aligned.m8n8.x4.shared.b16 {%0,%1,%2,%3}, [%4];"
                 : "=r"(r0), "=r"(r1), "=r"(r2), "=r"(r3) : "r"(addr));
}

__device__ __forceinline__ void cp16p(uint32_t dst, const void* src, int sz) {
    asm volatile("cp.async.cg.shared.global [%0], [%1], 16, %2;"
                 :: "r"(dst), "l"(src), "r"(sz) : "memory");
}
#define CP_COMMIT() asm volatile("cp.async.commit_group;" ::: "memory")
#define CP_WAIT0()  asm volatile("cp.async.wait_group 0;" ::: "memory")

// ---------------- CSR build ----------------
__global__ void k_count(const int* __restrict__ src, int ecount) {
    int e = blockIdx.x * blockDim.x + threadIdx.x;
    if (e < ecount) atomicAdd(&g_deg[src[e]], 1);
}
__global__ void k_scan1(int n) {
    __shared__ int s[512];
    int i = blockIdx.x * 512 + threadIdx.x;
    s[threadIdx.x] = (i < n) ? g_deg[i] : 0;
    __syncthreads();
#pragma unroll
    for (int off = 1; off < 512; off <<= 1) {
        int t = 0;
        if ((int)threadIdx.x >= off) t = s[threadIdx.x - off];
        __syncthreads();
        s[threadIdx.x] += t;
        __syncthreads();
    }
    if (i < n) g_tmpscan[i] = s[threadIdx.x];
    if (threadIdx.x == 511) g_blocksum[blockIdx.x] = s[511];
}
// merged scan2+scan3
__global__ void k_scan23(int nb, int n) {
    __shared__ int sh[128];
    __shared__ int orig[128];
    int t = threadIdx.x;
    if (t < 128) {
        int v = (t < nb) ? g_blocksum[t] : 0;
        sh[t] = v;
        orig[t] = v;
    }
    __syncthreads();
#pragma unroll
    for (int off = 1; off < 128; off <<= 1) {
        int x = 0;
        if (t < 128 && t >= off) x = sh[t - off];
        __syncthreads();
        if (t < 128) sh[t] += x;
        __syncthreads();
    }
    int i = blockIdx.x * 256 + t;
    if (i < n) {
        int blk = i >> 9;
        int r = g_tmpscan[i] - g_deg[i] + (sh[blk] - orig[blk]);
        g_rowptr[i] = r;
        g_pos[i] = r;
    }
    if (blockIdx.x == 0 && t == 0) g_rowptr[n] = sh[127];
}
__global__ void k_fill(const int* __restrict__ src, const int* __restrict__ dst, int ecount) {
    int e = blockIdx.x * blockDim.x + threadIdx.x;
    if (e >= ecount) return;
    int idx = atomicAdd(&g_pos[src[e]], 1);
    g_edges[idx] = make_int2(dst[e], e);
}

// Per-node gather with 8-lane groups; per-lane split writes.
__global__ void k_node(const int* __restrict__ x_ids, const float* __restrict__ attr, int n) {
    int gid = (blockIdx.x * blockDim.x + threadIdx.x) >> 3;
    int sl = threadIdx.x & 7;
    if (gid >= n) return;
    int e0 = g_rowptr[gid], e1 = g_rowptr[gid + 1];
    float a[9];
#pragma unroll
    for (int j = 0; j < 9; j++) a[j] = 0.f;
    int bc = 0;
    for (int e = e0 + sl; e < e1; e += 8) {
        int2 ce = g_edges[e];
        bc += x_ids[ce.x];
        const float* ap = attr + (size_t)ce.y * 9;
#pragma unroll
        for (int j = 0; j < 9; j++) a[j] += ap[j];
    }
#pragma unroll
    for (int o = 4; o > 0; o >>= 1) {
#pragma unroll
        for (int j = 0; j < 9; j++) a[j] += __shfl_xor_sync(0xffffffff, a[j], o);
        bc += __shfl_xor_sync(0xffffffff, bc, o);
    }
    a[7] += 1.0f;                                   // self-loop one-hot
    float dp1 = (float)(e1 - e0 + 1);
    float bfull = (float)(bc + x_ids[gid]);
    float t[16];
#pragma unroll
    for (int j = 0; j < 9; j++) t[j] = a[j];
    t[9] = dp1; t[10] = 1.f;
    t[11] = 0.f; t[12] = 0.f; t[13] = 0.f; t[14] = 0.f; t[15] = 0.f;
    float a0v[16];
    a0v[0] = dp1 - bfull;
    a0v[1] = bfull;
#pragma unroll
    for (int j = 0; j < 9; j++) a0v[2 + j] = a[j];
    a0v[11] = dp1; a0v[12] = 1.f;
    a0v[13] = 0.f; a0v[14] = 0.f; a0v[15] = 0.f;
    uint32_t h, l;
    splitpack(t[2 * sl], t[2 * sl + 1], h, l);
    g_AEh[(size_t)gid * KAU + 64 + sl] = h;
    g_AEl[(size_t)gid * KAU + 64 + sl] = l;
    splitpack(a0v[2 * sl], a0v[2 * sl + 1], h, l);
    g_A0h[(size_t)gid * K0P + sl] = h;
    g_A0l[(size_t)gid * K0P + sl] = l;
}

// ---------------- fused init: deg-zero + stats-zero + weight preps ----------------
__device__ __forceinline__ float w0row(int row, int col,
                                       const float* node_emb, const float* enc_w,
                                       const float* enc_b, const float* w1,
                                       const float* b1) {
    float val = 0.f;
    if (row < 2) {
        for (int k = 0; k < H; k++) val += node_emb[row * H + k] * w1[k * H2 + col];
    } else if (row < 11) {
        int j = row - 2;
        for (int k = 0; k < H; k++) val += enc_w[j * H + k] * w1[(H + k) * H2 + col];
    } else if (row == 11) {
        for (int k = 0; k < H; k++) val += enc_b[k] * w1[(H + k) * H2 + col];
    } else if (row == 12) {
        val = b1[col];
    }
    return val;
}
__device__ __forceinline__ float w1row(int row, int col,
                                       const float* enc_w, const float* enc_b,
                                       const float* w1, const float* b1) {
    const float* w1L = w1 + H2 * H2;
    float val = 0.f;
    if (row < 128) {
        val = w1L[row * H2 + col];
    } else if (row < 137) {
        int j = row - 128;
        for (int k = 0; k < H; k++) val += enc_w[9 * H + j * H + k] * w1L[(H + k) * H2 + col];
    } else if (row == 137) {
        for (int k = 0; k < H; k++) val += enc_b[H + k] * w1L[(H + k) * H2 + col];
    } else if (row == 138) {
        val = b1[H2 + col];
    }
    return val;
}

#define NBZ 196
__global__ void k_init(const float* __restrict__ node_emb, const float* __restrict__ enc_w,
                       const float* __restrict__ enc_b, const float* __restrict__ w1,
                       const float* __restrict__ b1, const float* __restrict__ w2, int n) {
    int b = blockIdx.x, tid = threadIdx.x;
    if (b < NBZ) {
        int i = b * 256 + tid;
        if (i < n) g_deg[i] = 0;
        if (i < 2 * H2) g_stats[i] = 0.f;
        return;
    }
    if (b < NBZ + 8) {               // W0 (bf16 split)
        int item = (b - NBZ) * 256 + tid;
        int nn = item >> 3, kp = item & 7;
        float v0 = w0row(2 * kp, nn, node_emb, enc_w, enc_b, w1, b1);
        float v1 = w0row(2 * kp + 1, nn, node_emb, enc_w, enc_b, w1, b1);
        uint32_t h, l;
        splitpack(v0, v1, h, l);
        g_W0h[nn * K0P + kp] = h;
        g_W0l[nn * K0P + kp] = l;
        return;
    }
    if (b < NBZ + 8 + 72) {          // W1 (bf16 split)
        int item = (b - NBZ - 8) * 256 + tid;
        int nn = item / KAU, kp = item - nn * KAU;
        float v0 = w1row(2 * kp, nn, enc_w, enc_b, w1, b1);
        float v1 = w1row(2 * kp + 1, nn, enc_w, enc_b, w1, b1);
        uint32_t h, l;
        splitpack(v0, v1, h, l);
        g_W1h[nn * KAU + kp] = h;
        g_W1l[nn * KAU + kp] = l;
        return;
    }
    {                                // W2 (fp16 split, x64 scale)
        int item = (b - NBZ - 80) * 256 + tid;
        if (item >= 2 * 128 * 128) return;
        int layer = item >> 14;
        int r = item & 16383;
        int nn = r >> 7, kp = r & 127;
        const float* w = w2 + (size_t)layer * H2 * H;
        float v0 = w[(2 * kp) * H + nn] * 64.f;
        float v1 = w[(2 * kp + 1) * H + nn] * 64.f;
        uint32_t h, l;
        splitpack_f16(v0, v1, h, l);
        g_W2h[item] = h;
        g_W2l[item] = l;
    }
}

// ---------------- z-GEMM: compensated bf16 3-pass, pre-split A/B, KPT=8, B via ldsm ----------------
__global__ void __launch_bounds__(256, 2)
zgemm(const uint32_t* __restrict__ Ah, const uint32_t* __restrict__ Al, int ldau,
      const uint32_t* __restrict__ Bh, const uint32_t* __restrict__ Bl, int ldku,
      float* __restrict__ C, int M, int K) {
    constexpr int KPT = 8;
    constexpr int S = KPT + 4;
    constexpr int ABUF = 128 * S * 4;
    constexpr int ASEC = 2 * ABUF;
    extern __shared__ __align__(16) char dsm[];
    uint32_t* aHp = (uint32_t*)dsm;
    uint32_t* bHp = (uint32_t*)(dsm + 2 * ASEC);

    int tid = threadIdx.x, wid = tid >> 5, lane = tid & 31;
    int qid = lane >> 2, rid = lane & 3;
    int warp_m = wid & 1, warp_n = wid >> 1;
    int m0 = blockIdx.x * 128, n0 = blockIdx.y * 128;

    float acc[4][4][4];
#pragma unroll
    for (int i = 0; i < 4; i++)
#pragma unroll
        for (int j = 0; j < 4; j++)
#pragma unroll
            for (int q = 0; q < 4; q++) acc[i][j][q] = 0.f;

    int row = tid >> 1;
    int half = tid & 1;
    int kp0 = half * 4;
    int gm = m0 + row;
    bool amv = gm < M;
    int gmc = amv ? gm : (M - 1);
    int azA = amv ? 16 : 0;
    uint32_t sA = smem_u32(aHp) + (uint32_t)(row * S + kp0) * 4;
    uint32_t sB = smem_u32(bHp) + (uint32_t)(row * S + kp0) * 4;
    const uint32_t* gBh = Bh + (size_t)(n0 + row) * ldku + kp0;
    const uint32_t* gBl = Bl + (size_t)(n0 + row) * ldku + kp0;
    const uint32_t* gAh = Ah + (size_t)gmc * ldau + kp0;
    const uint32_t* gAl = Al + (size_t)gmc * ldau + kp0;

    // B ldmatrix addresses: matrix m=lane>>3, nt=(m>>1), kblk=(m&1), row=lane&7
    uint32_t bA0 = smem_u32(bHp) +
        (uint32_t)(((warp_n * 32 + (lane >> 4) * 8 + (lane & 7)) * S + ((lane >> 3) & 1) * 4) * 4);

    int nsteps = K / 16;

    cp16p(sA, gAh, azA);
    cp16p(sA + ASEC, gAl, azA);
    cp16p(sB, gBh, 16);
    cp16p(sB + ASEC, gBl, 16);
    CP_COMMIT();

    int bo = 0;
    for (int s = 0; s < nsteps; s++) {
        CP_WAIT0();
        __syncthreads();
        if (s + 1 < nsteps) {
            int nb = bo ^ ABUF;
            int ko = (s + 1) * KPT;
            cp16p(sA + nb, gAh + ko, azA);
            cp16p(sA + nb + ASEC, gAl + ko, azA);
            cp16p(sB + nb, gBh + ko, 16);
            cp16p(sB + nb + ASEC, gBl + ko, 16);
            CP_COMMIT();
        }
        uint32_t sa_h = smem_u32(aHp) + bo +
            (uint32_t)(((warp_m * 64 + (lane & 15)) * S + ((lane & 16) ? 4 : 0)) * 4);
        uint32_t bb = bA0 + bo;
        uint32_t bfh[4][2], bfl[4][2];
        ldsm4(bfh[0][0], bfh[0][1], bfh[1][0], bfh[1][1], bb);
        ldsm4(bfh[2][0], bfh[2][1], bfh[3][0], bfh[3][1], bb + 16 * S * 4);
        ldsm4(bfl[0][0], bfl[0][1], bfl[1][0], bfl[1][1], bb + ASEC);
        ldsm4(bfl[2][0], bfl[2][1], bfl[3][0], bfl[3][1], bb + ASEC + 16 * S * 4);
#pragma unroll
        for (int mt = 0; mt < 4; mt++) {
            uint32_t ah[4], al[4];
            uint32_t ad = sa_h + mt * (16 * S * 4);
            ldsm4(ah[0], ah[1], ah[2], ah[3], ad);
            ldsm4(al[0], al[1], al[2], al[3], ad + ASEC);
#pragma unroll
            for (int nt = 0; nt < 4; nt++) {
                mma16(acc[mt][nt], ah, bfh[nt]);
                mma16(acc[mt][nt], ah, bfl[nt]);
                mma16(acc[mt][nt], al, bfh[nt]);
            }
        }
        __syncthreads();
        bo ^= ABUF;
    }

    int m_base = m0 + warp_m * 64;
    int n_base = n0 + warp_n * 32;

#pragma unroll
    for (int mt = 0; mt < 4; mt++) {
        int r0g = m_base + mt * 16 + qid;
        int r1g = r0g + 8;
#pragma unroll
        for (int nt = 0; nt < 4; nt++) {
            int cg = n_base + nt * 8 + rid * 2;
            if (r0g < M) *(float2*)(C + (size_t)r0g * H2 + cg)
                = make_float2(acc[mt][nt][0], acc[mt][nt][1]);
            if (r1g < M) *(float2*)(C + (size_t)r1g * H2 + cg)
                = make_float2(acc[mt][nt][2], acc[mt][nt][3]);
        }
    }

#pragma unroll
    for (int nt = 0; nt < 4; nt++) {
        float s0 = 0.f, q0 = 0.f, s1 = 0.f, q1 = 0.f;
#pragma unroll
        for (int mt = 0; mt < 4; mt++) {
            int r0g = m_base + mt * 16 + qid;
            const float* c = acc[mt][nt];
            if (r0g < M)     { s0 += c[0]; q0 += c[0] * c[0]; s1 += c[1]; q1 += c[1] * c[1]; }
            if (r0g + 8 < M) { s0 += c[2]; q0 += c[2] * c[2]; s1 += c[3]; q1 += c[3] * c[3]; }
        }
#pragma unroll
        for (int o = 4; o < 32; o <<= 1) {
            s0 += __shfl_xor_sync(0xffffffff, s0, o);
            q0 += __shfl_xor_sync(0xffffffff, q0, o);
            s1 += __shfl_xor_sync(0xffffffff, s1, o);
            q1 += __shfl_xor_sync(0xffffffff, q1, o);
        }
        if (lane < 4) {
            int cg = n_base + nt * 8 + lane * 2;
            atomicAdd(&g_stats[cg], s0);
            atomicAdd(&g_stats[H2 + cg], q0);
            atomicAdd(&g_stats[cg + 1], s1);
            atomicAdd(&g_stats[H2 + cg + 1], q1);
        }
    }
}

// ---------------- h-GEMM: fp16 2-pass, B via ldsm ----------------
#define HS   20
#define HABUF (128 * HS * 4)
template <bool STOREH16>
__global__ void __launch_bounds__(256, 2)
hgemm(const float* __restrict__ Af,
      const uint32_t* __restrict__ Bh, const uint32_t* __restrict__ Bl,
      float* __restrict__ C, uint32_t* __restrict__ C16, int M,
      const float* __restrict__ bias, int do_relu,
      const float* __restrict__ bng, const float* __restrict__ bnb) {
    extern __shared__ __align__(16) char dsm[];
    uint32_t* aP  = (uint32_t*)dsm;
    uint32_t* bHp = (uint32_t*)(dsm + 2 * HABUF);
    __shared__ float s_sc[H2], s_sh[H2];

    int tid = threadIdx.x, wid = tid >> 5, lane = tid & 31;
    int qid = lane >> 2, rid = lane & 3;
    int warp_m = wid & 1, warp_n = wid >> 1;
    int m0 = blockIdx.x * 128;

    {
        float inv = 1.f / (float)M;
        float mu = g_stats[tid] * inv;
        float var = g_stats[H2 + tid] * inv - mu * mu;
        float rs = rsqrtf(var + 1e-5f);
        float sc = bng[tid] * rs;
        s_sc[tid] = sc;
        s_sh[tid] = bnb[tid] - mu * sc;
    }

    float acc[4][4][4];
#pragma unroll
    for (int i = 0; i < 4; i++)
#pragma unroll
        for (int j = 0; j < 4; j++)
#pragma unroll
            for (int q = 0; q < 4; q++) acc[i][j][q] = 0.f;

    int row = tid >> 1;
    int half = tid & 1;
    int gm = m0 + row;
    bool amv = gm < M;
    int gmc = amv ? gm : (M - 1);
    uint32_t sB = smem_u32(bHp) + (uint32_t)(row * HS + half * 8) * 4;
    const uint32_t* gBh = Bh + (size_t)row * 128 + half * 8;
    const uint32_t* gBl = Bl + (size_t)row * 128 + half * 8;
    const float* gAf = Af + (size_t)gmc * H2 + half * 16;

    // B ldmatrix addresses
    uint32_t bB0 = smem_u32(bHp) +
        (uint32_t)(((warp_n * 32 + (lane >> 4) * 8 + (lane & 7)) * HS + ((lane >> 3) & 1) * 4) * 4);

    const float4 z4f = make_float4(0.f, 0.f, 0.f, 0.f);
    float4 pz[4];

#pragma unroll
    for (int i = 0; i < 4; i++) pz[i] = *(const float4*)(gAf + i * 4);
#pragma unroll
    for (int i = 0; i < 2; i++) {
        cp16p(sB + i * 16, gBh + i * 4, 16);
        cp16p(sB + 2 * HABUF + i * 16, gBl + i * 4, 16);
    }
    CP_COMMIT();
    __syncthreads();

    int bo = 0;
    for (int s = 0; s < 8; s++) {
        CP_WAIT0();
        {
            int gkb = s * 32 + half * 16;
            uint32_t* dA = aP + (bo >> 2) + row * HS + half * 8;
#pragma unroll
            for (int i = 0; i < 4; i++) {
                float4 v = pz[i];
                int gk = gkb + i * 4;
                v.x = fmaxf(fmaf(v.x, s_sc[gk + 0], s_sh[gk + 0]), 0.f);
                v.y = fmaxf(fmaf(v.y, s_sc[gk + 1], s_sh[gk + 1]), 0.f);
                v.z = fmaxf(fmaf(v.z, s_sc[gk + 2], s_sh[gk + 2]), 0.f);
                v.w = fmaxf(fmaf(v.w, s_sc[gk + 3], s_sh[gk + 3]), 0.f);
                if (!amv) { v.x = v.y = v.z = v.w = 0.f; }
                dA[i * 2]     = pack_f16x2(v.x, v.y);
                dA[i * 2 + 1] = pack_f16x2(v.z, v.w);
            }
        }
        __syncthreads();
        if (s + 1 < 8) {
            int nb = bo ^ HABUF;
            int ko = (s + 1) * 16;
#pragma unroll
            for (int i = 0; i < 2; i++) {
                cp16p(sB + nb + i * 16, gBh + ko + i * 4, 16);
                cp16p(sB + nb + 2 * HABUF + i * 16, gBl + ko + i * 4, 16);
            }
            CP_COMMIT();
            const float* zp = gAf + (size_t)(s + 1) * 32;
#pragma unroll
            for (int i = 0; i < 4; i++)
                pz[i] = amv ? *(const float4*)(zp + i * 4) : z4f;
        }

        uint32_t sa = smem_u32(aP) + bo +
            (uint32_t)(((warp_m * 64 + (lane & 15)) * HS + ((lane & 16) ? 4 : 0)) * 4);
#pragma unroll
        for (int sub = 0; sub < 2; sub++) {
            uint32_t bb = bB0 + bo + sub * 32;
            uint32_t bfh[4][2], bfl[4][2];
            ldsm4(bfh[0][0], bfh[0][1], bfh[1][0], bfh[1][1], bb);
            ldsm4(bfh[2][0], bfh[2][1], bfh[3][0], bfh[3][1], bb + 16 * HS * 4);
            ldsm4(bfl[0][0], bfl[0][1], bfl[1][0], bfl[1][1], bb + 2 * HABUF);
            ldsm4(bfl[2][0], bfl[2][1], bfl[3][0], bfl[3][1], bb + 2 * HABUF + 16 * HS * 4);
#pragma unroll
            for (int mt = 0; mt < 4; mt++) {
                uint32_t ah[4];
                ldsm4(ah[0], ah[1], ah[2], ah[3], sa + sub * 32 + mt * (16 * HS * 4));
#pragma unroll
                for (int nt = 0; nt < 4; nt++) {
                    mma16f(acc[mt][nt], ah, bfh[nt]);
                    mma16f(acc[mt][nt], ah, bfl[nt]);
                }
            }
        }
        __syncthreads();
        bo ^= HABUF;
    }

    int m_base = m0 + warp_m * 64;
    int n_base = warp_n * 32;
    const float inv64 = 0.015625f;

#pragma unroll
    for (int mt = 0; mt < 4; mt++) {
        int r0g = m_base + mt * 16 + qid;
        int r1g = r0g + 8;
#pragma unroll
        for (int nt = 0; nt < 4; nt++) {
            int cg = n_base + nt * 8 + rid * 2;
            float b0v = bias[cg], b1v = bias[cg + 1];
            float v0 = fmaf(acc[mt][nt][0], inv64, b0v);
            float v1 = fmaf(acc[mt][nt][1], inv64, b1v);
            float v2 = fmaf(acc[mt][nt][2], inv64, b0v);
            float v3 = fmaf(acc[mt][nt][3], inv64, b1v);
            if (do_relu) {
                v0 = fmaxf(v0, 0.f); v1 = fmaxf(v1, 0.f);
                v2 = fmaxf(v2, 0.f); v3 = fmaxf(v3, 0.f);
            }
            if (STOREH16) {
                if (r0g < M) C16[(size_t)r0g * 64 + (cg >> 1)] = pack_f16x2(v0, v1);
                if (r1g < M) C16[(size_t)r1g * 64 + (cg >> 1)] = pack_f16x2(v2, v3);
            } else {
                if (r0g < M) *(float2*)(C + (size_t)r0g * H + cg) = make_float2(v0, v1);
                if (r1g < M) *(float2*)(C + (size_t)r1g * H + cg) = make_float2(v2, v3);
            }
        }
    }
}

// ---------------- SpMM: fp16 gather of h0; write bf16-split agg; re-zero stats ----------------
__global__ void k_spmm(int n) {
    int t0 = blockIdx.x * blockDim.x + threadIdx.x;
    if (t0 < 2 * H2) g_stats[t0] = 0.f;
    int wid = t0 >> 5;
    int lane = threadIdx.x & 31;
    if (wid >= n) return;
    const uint2* h2 = (const uint2*)g_h16;
    uint2 sv = h2[(size_t)wid * 32 + lane];
    float2 f0 = __half22float2(*(__half2*)&sv.x);
    float2 f1 = __half22float2(*(__half2*)&sv.y);
    float4 acc = make_float4(f0.x, f0.y, f1.x, f1.y);
    int e0 = g_rowptr[wid], e1 = g_rowptr[wid + 1];
    for (int e = e0; e < e1; e++) {
        int c = g_edges[e].x;
        uint2 hv = h2[(size_t)c * 32 + lane];
        float2 a0 = __half22float2(*(__half2*)&hv.x);
        float2 a1 = __half22float2(*(__half2*)&hv.y);
        acc.x += a0.x; acc.y += a0.y; acc.z += a1.x; acc.w += a1.y;
    }
    uint32_t h0, l0, h1, l1;
    splitpack(acc.x, acc.y, h0, l0);
    splitpack(acc.z, acc.w, h1, l1);
    size_t base = (size_t)wid * KAU + 2 * lane;
    *(uint2*)&g_AEh[base] = make_uint2(h0, h1);
    *(uint2*)&g_AEl[base] = make_uint2(l0, l1);
}

// ---------------- fused head ----------------
__global__ void k_head(const int* __restrict__ batch, const float* __restrict__ disc_w, int n) {
    __shared__ float srow[H];
    int g = blockIdx.x;
    int c = threadIdx.x;
    int lo = 0, hi = n;
    while (lo < hi) { int m = (lo + hi) >> 1; if (batch[m] < g) lo = m + 1; else hi = m; }
    int lo2 = lo, hi2 = n;
    while (lo2 < hi2) { int m = (lo2 + hi2) >> 1; if (batch[m] < g + 1) lo2 = m + 1; else hi2 = m; }
    float s = 0.f;
    for (int r = lo; r < lo2; r++) s += g_h[(size_t)r * H + c];
    float cnt = fmaxf((float)(lo2 - lo), 1.f);
    float sm = 1.f / (1.f + expf(-s / cnt));
    srow[c] = sm;
    __syncthreads();
    float acc = 0.f;
    for (int k = 0; k < H; k++) acc = fmaf(srow[k], disc_w[k * H + c], acc);
    g_s2[g * H + c] = acc;
}

// 8-lane groups: 4 nodes per warp
__global__ void k_out(const int* __restrict__ batch, float* __restrict__ out, int n) {
    int gid = (blockIdx.x * blockDim.x + threadIdx.x) >> 3;
    int sl = threadIdx.x & 7;
    if (gid >= n) return;
    int g = batch[gid];
    int g2 = (g + 1) & (GG - 1);
    const float4* h4 = (const float4*)g_h;
    const float4* s4 = (const float4*)g_s2;
    float p = 0.f, q = 0.f;
#pragma unroll
    for (int i = 0; i < 4; i++) {
        float4 hv = h4[(size_t)gid * 32 + sl * 4 + i];
        float4 av = s4[(size_t)g * 32 + sl * 4 + i];
        float4 bv = s4[(size_t)g2 * 32 + sl * 4 + i];
        p += hv.x * av.x + hv.y * av.y + hv.z * av.z + hv.w * av.w;
        q += hv.x * bv.x + hv.y * bv.y + hv.z * bv.z + hv.w * bv.w;
    }
#pragma unroll
    for (int off = 4; off > 0; off >>= 1) {
        p += __shfl_xor_sync(0xffffffff, p, off);
        q += __shfl_xor_sync(0xffffffff, q, off);
    }
    if (sl == 0) { out[gid] = p; out[n + gid] = q; }
}

// ---------------- host ----------------
extern "C" void kernel_launch(void* const* d_in, const int* in_sizes, int n_in,
                              void* d_out, int out_size) {
    const int*   x_ids     = (const int*)d_in[0];
    const int*   ei        = (const int*)d_in[1];
    const int*   batch     = (const int*)d_in[2];
    const float* edge_attr = (const float*)d_in[3];
    const float* node_emb  = (const float*)d_in[4];
    const float* enc_w     = (const float*)d_in[5];
    const float* enc_b     = (const float*)d_in[6];
    const float* w1        = (const float*)d_in[7];
    const float* b1        = (const float*)d_in[8];
    const float* bn_g      = (const float*)d_in[9];
    const float* bn_b      = (const float*)d_in[10];
    const float* w2        = (const float*)d_in[11];
    const float* b2        = (const float*)d_in[12];
    const float* disc_w    = (const float*)d_in[13];
    float* out = (float*)d_out;

    int n  = in_sizes[0];
    int ec = in_sizes[1] / 2;
    const int* src = ei;
    const int* dst = ei + ec;

    const int SMZ = 4 * 2 * 128 * 12 * 4;   // 49152
    const int SMH = 6 * HABUF;              // 61440
    cudaFuncSetAttribute(zgemm, cudaFuncAttributeMaxDynamicSharedMemorySize, SMZ);
    cudaFuncSetAttribute(hgemm<true>, cudaFuncAttributeMaxDynamicSharedMemorySize, SMH);
    cudaFuncSetAttribute(hgemm<false>, cudaFuncAttributeMaxDynamicSharedMemorySize, SMH);

    float *p_z, *p_h;
    uint32_t *p_A0h, *p_A0l, *p_AEh, *p_AEl;
    uint32_t *p_W0h, *p_W0l, *p_W1h, *p_W1l, *p_W2h, *p_W2l, *p_h16;
    cudaGetSymbolAddress((void**)&p_z,   g_z);
    cudaGetSymbolAddress((void**)&p_h,   g_h);
    cudaGetSymbolAddress((void**)&p_h16, g_h16);
    cudaGetSymbolAddress((void**)&p_A0h, g_A0h);
    cudaGetSymbolAddress((void**)&p_A0l, g_A0l);
    cudaGetSymbolAddress((void**)&p_AEh, g_AEh);
    cudaGetSymbolAddress((void**)&p_AEl, g_AEl);
    cudaGetSymbolAddress((void**)&p_W0h, g_W0h);
    cudaGetSymbolAddress((void**)&p_W0l, g_W0l);
    cudaGetSymbolAddress((void**)&p_W1h, g_W1h);
    cudaGetSymbolAddress((void**)&p_W1l, g_W1l);
    cudaGetSymbolAddress((void**)&p_W2h, g_W2h);
    cudaGetSymbolAddress((void**)&p_W2l, g_W2l);

    int eb    = (ec + 255) / 256;
    int nb512 = (n + 511) / 512;
    int nb    = (n + 255) / 256;
    int mb    = (n + 127) / 128;
    int warpsB = (n * 32 + 255) / 256;
    int nodeB  = (n * 8 + 255) / 256;
    int initB  = NBZ + 8 + 72 + 128;

    // --- init + CSR + node features ---
    k_init<<<initB, 256>>>(node_emb, enc_w, enc_b, w1, b1, w2, n);
    k_count<<<eb, 256>>>(src, ec);
    k_scan1<<<nb512, 512>>>(n);
    k_scan23<<<nb, 256>>>(nb512, n);
    k_fill<<<eb, 256>>>(src, dst, ec);
    k_node<<<nodeB, 256>>>(x_ids, edge_attr, n);

    // --- layer 0 ---
    zgemm<<<dim3(mb, 2), 256, SMZ>>>(p_A0h, p_A0l, K0P, p_W0h, p_W0l, K0P, p_z, n, 16);
    hgemm<true><<<dim3(mb, 1), 256, SMH>>>(p_z, p_W2h, p_W2l, nullptr, p_h16, n,
                                           b2, 1, bn_g, bn_b);

    // --- layer 1 ---
    k_spmm<<<warpsB, 256>>>(n);
    zgemm<<<dim3(mb, 2), 256, SMZ>>>(p_AEh, p_AEl, KAU, p_W1h, p_W1l, KAU, p_z, n, 144);
    hgemm<false><<<dim3(mb, 1), 256, SMH>>>(p_z, p_W2h + 128 * 128, p_W2l + 128 * 128,
                                            p_h, nullptr, n, b2 + H, 0,
                                            bn_g + H2, bn_b + H2);

    // --- head ---
    k_head<<<GG, H>>>(batch, disc_w, n);
    k_out<<<nodeB, 256>>>(batch, out, n);
}